// round 16
// baseline (speedup 1.0000x reference)
#include <cuda_runtime.h>
#include <cuda_bf16.h>
#include <math_constants.h>
#include <cstdint>

#define BATCH    1024
#define NHID     1024
#define NCLASSES 224
#define NPC      225
#define DSEG     8
#define DLEN     128      // NHID / DSEG
#define SCH      8        // samples per chunk (bottom)
#define KLEN     128
#define TD       16       // d-rows per cp.async weight tile
#define NTILE    (DLEN / TD)                    // 8
#define BOT_BLOCKS (NCLASSES * DSEG * 2)        // 3584 (2 chunk-blocks per class/seg)
#define TOP_BLOCKS 512                          // 64 rowgroups x 8 ksegs
#define ALL_BLOCKS (BOT_BLOCKS + TOP_BLOCKS)    // 4096

typedef unsigned long long ull;

// ---------------- scratch (device globals) ----------------------------------
__device__ float g_top_logits[BATCH * NCLASSES];
__device__ float g_bot_logits[BATCH * NPC];
__device__ int   g_pos_top[BATCH];
__device__ int   g_pos_bottom[BATCH];
__device__ int   g_count[NCLASSES];
__device__ int   g_offset[NCLASSES + 1];
__device__ int   g_sorted[BATCH];

// ---------------- cp.async helpers ------------------------------------------
__device__ __forceinline__ void cp16(uint32_t dst_smem, const void* src) {
    asm volatile("cp.async.cg.shared.global [%0], [%1], 16;"
                 :: "r"(dst_smem), "l"(src));
}
__device__ __forceinline__ void cp_commit() {
    asm volatile("cp.async.commit_group;");
}
__device__ __forceinline__ void cp_wait1() {
    asm volatile("cp.async.wait_group 1;");
}

// ---------------- 1: init — zero accumulators + (block 0) label prep --------
__global__ void __launch_bounds__(1024) k_init(const void* __restrict__ labels_raw)
{
    int t = threadIdx.x;

    if (blockIdx.x == 0) {
        __shared__ int s_count[NCLASSES];
        __shared__ int s_off[NCLASSES];
        if (t < NCLASSES) s_count[t] = 0;
        __syncthreads();

        // detect int64 vs int32 labels (odd 32-bit words all zero => int64 LE)
        const unsigned int* w = (const unsigned int*)labels_raw;
        bool is64 = ((w[1] | w[3] | w[5] | w[7] | w[9] | w[11] | w[13] | w[15]) == 0u);
        unsigned int lab = is64 ? (unsigned int)(((const ull*)labels_raw)[t])
                                : (unsigned int)(((const unsigned int*)labels_raw)[t]);
        int pt = (int)(lab / NPC);
        int pb = (int)(lab % NPC);
        g_pos_top[t]    = pt;
        g_pos_bottom[t] = pb;
        atomicAdd(&s_count[pt], 1);
        __syncthreads();

        if (t < 32) {
            int base = t * 7;
            int v[7], loc[7];
            int sum = 0;
#pragma unroll
            for (int i = 0; i < 7; i++) v[i] = s_count[base + i];
#pragma unroll
            for (int i = 0; i < 7; i++) { loc[i] = sum; sum += v[i]; }
            int run = sum;
#pragma unroll
            for (int o = 1; o < 32; o <<= 1) {
                int nb = __shfl_up_sync(0xFFFFFFFFu, run, o);
                if (t >= o) run += nb;
            }
            int excl = run - sum;
#pragma unroll
            for (int i = 0; i < 7; i++) {
                s_off[base + i]    = excl + loc[i];
                g_offset[base + i] = excl + loc[i];
            }
            if (t == 31) g_offset[NCLASSES] = excl + sum;
        }
        __syncthreads();
        if (t < NCLASSES) g_count[t] = s_count[t];
        int p = atomicAdd(&s_off[pt], 1);
        g_sorted[p] = t;
    }

    // all blocks: zero logit accumulators (float4 stores)
    int i = blockIdx.x * 1024 + t;
    int stride = gridDim.x * 1024;
    float4 z = make_float4(0.f, 0.f, 0.f, 0.f);
    for (int j = i; j < BATCH * NCLASSES / 4; j += stride)
        ((float4*)g_top_logits)[j] = z;
    for (int j = i; j < BATCH * NPC / 4; j += stride)
        ((float4*)g_bot_logits)[j] = z;
}

// ---------------- 2: fused main — bottom (3-buf cp.async W) + top GEMM -------
// grid 4096; per group of 8 bids: 7 bottom + 1 top.
// bottom index b in [0,3584): b = (c*8 + seg)*2 + chunk.
__global__ void __launch_bounds__(128) k_main(
    const float* __restrict__ X,    // [BATCH, NHID]
    const float* __restrict__ Wt,   // [NHID, NCLASSES]
    const float* __restrict__ Wb)   // [NCLASSES, NHID, NPC]
{
    __shared__ __align__(16) union {
        struct {
            float Wsm[3][TD * NPC];   // 3 x 14.4 KB
            float Xs[SCH][DLEN];      // 4 KB
            int   ids[SCH];
        } b;                          // 47.3 KB
        struct { float Xs[16][KLEN]; float Ws[16][NCLASSES]; } tp;  // 22.5 KB
    } sm;

    int bx = blockIdx.x;
    int g  = bx >> 3;
    int r  = bx & 7;
    bool is_top = (r == 7);
    int t = threadIdx.x, warp = t >> 5, lane = t & 31;

    if (!is_top) {
        // ===================== bottom =====================
        int b     = g * 7 + r;          // 0..3583
        int chunk = b & 1;
        int cs    = b >> 1;             // c*8 + seg
        int c     = cs >> 3;
        int seg   = cs & 7;
        int n = g_count[c];
        int s_begin = chunk * SCH;
        if (s_begin >= n) return;       // spare chunk block: exit
        int base = g_offset[c];
        int d0   = seg * DLEN;

        int c0 = warp * 64 + lane;      // always < 224
        int c1 = c0 + 32;
        bool v1 = (c1 < NPC);
        int c1c = v1 ? c1 : 224;

        const float* W = Wb + (size_t)c * NHID * NPC + (size_t)d0 * NPC;
        uint32_t smW[3];
#pragma unroll
        for (int k = 0; k < 3; k++)
            smW[k] = (uint32_t)__cvta_generic_to_shared(&sm.b.Wsm[k][0]);
        uint32_t smX = (uint32_t)__cvta_generic_to_shared(&sm.b.Xs[0][0]);

        // chunk 0: one pass; chunk 1: all remaining passes (rare n>16)
        int s_end  = (chunk == 0) ? min(n, SCH) : n;
        for (int s0 = s_begin; s0 < s_end; s0 += SCH) {
            int ns = min(SCH, n - s0);
            __syncthreads();            // protect ids/Xs across outer iterations
            if (t < ns) sm.b.ids[t] = g_sorted[base + s0 + t];
            __syncthreads();

            // stage X rows via cp.async (part of tile-0's group);
            // zero-fill dead slots with STS (covered by first pipeline sync)
            for (int i = t; i < SCH * 32; i += 128) {
                int s = i >> 5, q = i & 31;
                if (s < ns)
                    cp16(smX + i * 16,
                         ((const float4*)(X + (size_t)sm.b.ids[s] * NHID + d0)) + q);
                else
                    ((float4*)&sm.b.Xs[0][0])[i] = make_float4(0.f, 0.f, 0.f, 0.f);
            }
            // prologue: prefetch weight tiles 0 and 1 (two groups)
            {
                const float4* src0 = (const float4*)W;
                for (int i = t; i < TD * NPC / 4; i += 128)
                    cp16(smW[0] + i * 16, src0 + i);
                cp_commit();            // group: X + tile0
                const float4* src1 = (const float4*)(W + (size_t)TD * NPC);
                for (int i = t; i < TD * NPC / 4; i += 128)
                    cp16(smW[1] + i * 16, src1 + i);
                cp_commit();            // group: tile1
            }

            float acc0[SCH], acc1[SCH];
#pragma unroll
            for (int s = 0; s < SCH; s++) { acc0[s] = 0.f; acc1[s] = 0.f; }

            for (int tile = 0; tile < NTILE; tile++) {
                cp_wait1();             // tile's own group landed (<=1 pending)
                __syncthreads();        // all threads' portions visible

                // prefetch tile+2 AFTER the barrier: overwrite of the buffer
                // consumed at (tile-1) is ordered behind everyone's consume.
                if (tile + 2 < NTILE) {
                    const float4* src = (const float4*)(W + (size_t)(tile + 2) * TD * NPC);
                    uint32_t dst = smW[(tile + 2) % 3];
                    for (int i = t; i < TD * NPC / 4; i += 128)
                        cp16(dst + i * 16, src + i);
                }
                cp_commit();

                const float* Wsm = sm.b.Wsm[tile % 3];
                int tbase = tile * TD;
#pragma unroll
                for (int dq = 0; dq < TD; dq += 4) {
                    float w0[4], w1[4];
#pragma unroll
                    for (int k = 0; k < 4; k++) {
                        w0[k] = Wsm[(dq + k) * NPC + c0];
                        w1[k] = Wsm[(dq + k) * NPC + c1c];
                    }
#pragma unroll
                    for (int s = 0; s < SCH; s++) {
                        float4 x = *(const float4*)&sm.b.Xs[s][tbase + dq];
                        acc0[s] += x.x * w0[0]; acc1[s] += x.x * w1[0];
                        acc0[s] += x.y * w0[1]; acc1[s] += x.y * w1[1];
                        acc0[s] += x.z * w0[2]; acc1[s] += x.z * w1[2];
                        acc0[s] += x.w * w0[3]; acc1[s] += x.w * w1[3];
                    }
                }
            }

            for (int s = 0; s < ns; s++) {
                int sid = sm.b.ids[s];
                atomicAdd(&g_bot_logits[sid * NPC + c0], acc0[s]);
                if (v1) atomicAdd(&g_bot_logits[sid * NPC + c1], acc1[s]);
            }
        }
    } else {
        // ===================== top GEMM =====================
        int tb = g;                      // 0..511
        int r0 = (tb >> 3) * 16;
        int k0 = (tb & 7) * KLEN;

        for (int i = t; i < 16 * 32; i += 128) {
            int rr = i >> 5, q = i & 31;
            ((float4*)&sm.tp.Xs[rr][0])[q] =
                ((const float4*)(X + (size_t)(r0 + rr) * NHID + k0))[q];
        }

        float acc[4][7];
#pragma unroll
        for (int rr = 0; rr < 4; rr++)
#pragma unroll
            for (int i = 0; i < 7; i++) acc[rr][i] = 0.f;

        for (int kc = 0; kc < KLEN; kc += 16) {
            __syncthreads();
            for (int i = t; i < 16 * NCLASSES; i += 128) {
                int kk = i / NCLASSES;
                int cc = i - kk * NCLASSES;
                sm.tp.Ws[kk][cc] = Wt[(size_t)(k0 + kc + kk) * NCLASSES + cc];
            }
            __syncthreads();
#pragma unroll
            for (int kq = 0; kq < 16; kq += 4) {
                float4 xv[4];
#pragma unroll
                for (int rr = 0; rr < 4; rr++)
                    xv[rr] = *(const float4*)&sm.tp.Xs[warp * 4 + rr][kc + kq];
                const float* xf = (const float*)xv;
#pragma unroll
                for (int j = 0; j < 4; j++) {
#pragma unroll
                    for (int i = 0; i < 7; i++) {
                        float wv = sm.tp.Ws[kq + j][lane + 32 * i];
#pragma unroll
                        for (int rr = 0; rr < 4; rr++)
                            acc[rr][i] += xf[rr * 4 + j] * wv;
                    }
                }
            }
        }

#pragma unroll
        for (int rr = 0; rr < 4; rr++) {
            int row = r0 + warp * 4 + rr;
#pragma unroll
            for (int i = 0; i < 7; i++)
                atomicAdd(&g_top_logits[row * NCLASSES + lane + 32 * i], acc[rr][i]);
        }
    }
}

// ---------------- block reduction helper (256 threads, 8 warps) --------------
__device__ __forceinline__ float blk_reduce(float v, bool is_max,
                                            int warp, int lane, float* red)
{
#pragma unroll
    for (int o = 16; o > 0; o >>= 1) {
        float u = __shfl_xor_sync(0xFFFFFFFFu, v, o);
        v = is_max ? fmaxf(v, u) : (v + u);
    }
    if (lane == 0) red[warp] = v;
    __syncthreads();
    if (warp == 0) {
        float x = (lane < 8) ? red[lane] : (is_max ? -CUDART_INF_F : 0.f);
#pragma unroll
        for (int o = 4; o > 0; o >>= 1) {
            float u = __shfl_xor_sync(0xFFFFFFFFu, x, o);
            x = is_max ? fmaxf(x, u) : (x + u);
        }
        if (lane == 0) red[8] = x;
    }
    __syncthreads();
    float r = red[8];
    __syncthreads();    // safe to reuse red[]
    return r;
}

// ---------------- 3: finish — block per sample, both softmaxes + output ------
__global__ void __launch_bounds__(256) k_finish(
    const float* __restrict__ bt,   // [224]
    const float* __restrict__ bb,   // [NCLASSES, NPC]
    float* __restrict__ out)
{
    __shared__ float red[9];
    __shared__ float s_etgt;

    int sid = blockIdx.x;
    int t = threadIdx.x, warp = t >> 5, lane = t & 31;
    int c  = g_pos_top[sid];
    int pb = g_pos_bottom[sid];

    float lt = (t < NCLASSES) ? (g_top_logits[sid * NCLASSES + t] + bt[t])
                              : -CUDART_INF_F;
    float vb = (t < NPC)      ? (g_bot_logits[sid * NPC + t] + bb[c * NPC + t])
                              : -CUDART_INF_F;

    float mxt = blk_reduce(lt, true, warp, lane, red);
    float et  = (t < NCLASSES) ? __expf(lt - mxt) : 0.f;
    if (t == c) s_etgt = et;
    float st  = blk_reduce(et, false, warp, lane, red);

    float mxb = blk_reduce(vb, true, warp, lane, red);
    float eb  = (t < NPC) ? __expf(vb - mxb) : 0.f;
    float sb  = blk_reduce(eb, false, warp, lane, red);

    if (t == pb)
        out[sid] = (s_etgt / st) * (eb / sb);
}

// ---------------- launch -----------------------------------------------------
extern "C" void kernel_launch(void* const* d_in, const int* in_sizes, int n_in,
                              void* d_out, int out_size)
{
    const float* X   = (const float*)d_in[0];   // [1024, 1024]
    const void*  lab = d_in[1];                 // [1024] int32/int64
    const float* Wt  = (const float*)d_in[2];   // [1024, 224]
    const float* bt  = (const float*)d_in[3];   // [224]
    const float* Wb  = (const float*)d_in[4];   // [224, 1024, 225]
    const float* bb  = (const float*)d_in[5];   // [224, 225]
    float* out = (float*)d_out;

    k_init<<<112, 1024>>>(lab);
    k_main<<<ALL_BLOCKS, 128>>>(X, Wt, Wb);
    k_finish<<<BATCH, 256>>>(bt, bb, out);
}

// round 17
// speedup vs baseline: 1.0380x; 1.0380x over previous
#include <cuda_runtime.h>
#include <cuda_bf16.h>
#include <math_constants.h>
#include <cstdint>

#define BATCH    1024
#define NHID     1024
#define NCLASSES 224
#define NPC      225
#define DSEG     8
#define DLEN     128      // NHID / DSEG
#define SCH      8        // samples per chunk (bottom)
#define KLEN     128
#define TD       16       // d-rows per weight tile
#define NTILE    (DLEN / TD)                    // 8
#define WBYTES   (TD * NPC * 4)                 // 14400 bytes, 16B-aligned
#define BOT_BLOCKS (NCLASSES * DSEG * 2)        // 3584 (2 chunk-blocks per class/seg)
#define TOP_BLOCKS 512                          // 64 rowgroups x 8 ksegs
#define ALL_BLOCKS (BOT_BLOCKS + TOP_BLOCKS)    // 4096

typedef unsigned long long ull;

// ---------------- scratch (device globals) ----------------------------------
__device__ float g_top_logits[BATCH * NCLASSES];
__device__ float g_bot_logits[BATCH * NPC];
__device__ int   g_pos_top[BATCH];
__device__ int   g_pos_bottom[BATCH];
__device__ int   g_count[NCLASSES];
__device__ int   g_offset[NCLASSES + 1];
__device__ int   g_sorted[BATCH];

// ---------------- TMA bulk + mbarrier helpers --------------------------------
__device__ __forceinline__ void mbar_init(uint32_t mbar, uint32_t cnt) {
    asm volatile("mbarrier.init.shared.b64 [%0], %1;" :: "r"(mbar), "r"(cnt) : "memory");
}
__device__ __forceinline__ void mbar_expect_tx(uint32_t mbar, uint32_t bytes) {
    asm volatile("mbarrier.arrive.expect_tx.shared.b64 _, [%0], %1;"
                 :: "r"(mbar), "r"(bytes) : "memory");
}
__device__ __forceinline__ void mbar_wait(uint32_t mbar, uint32_t parity) {
    asm volatile(
        "{\n\t"
        ".reg .pred P;\n\t"
        "WAIT_%=:\n\t"
        "mbarrier.try_wait.parity.acquire.cta.shared::cta.b64 P, [%0], %1, 0x989680;\n\t"
        "@P bra.uni DONE_%=;\n\t"
        "bra.uni WAIT_%=;\n\t"
        "DONE_%=:\n\t"
        "}"
        :: "r"(mbar), "r"(parity) : "memory");
}
__device__ __forceinline__ void tma_bulk_1d(uint32_t dst_smem, const void* src,
                                            uint32_t bytes, uint32_t mbar) {
    asm volatile(
        "cp.async.bulk.shared::cta.global.mbarrier::complete_tx::bytes "
        "[%0], [%1], %2, [%3];"
        :: "r"(dst_smem), "l"(src), "r"(bytes), "r"(mbar) : "memory");
}

// ---------------- 1: init — zero accumulators + (block 0) label prep --------
__global__ void __launch_bounds__(1024) k_init(const void* __restrict__ labels_raw)
{
    int t = threadIdx.x;

    if (blockIdx.x == 0) {
        __shared__ int s_count[NCLASSES];
        __shared__ int s_off[NCLASSES];
        if (t < NCLASSES) s_count[t] = 0;
        __syncthreads();

        // detect int64 vs int32 labels (odd 32-bit words all zero => int64 LE)
        const unsigned int* w = (const unsigned int*)labels_raw;
        bool is64 = ((w[1] | w[3] | w[5] | w[7] | w[9] | w[11] | w[13] | w[15]) == 0u);
        unsigned int lab = is64 ? (unsigned int)(((const ull*)labels_raw)[t])
                                : (unsigned int)(((const unsigned int*)labels_raw)[t]);
        int pt = (int)(lab / NPC);
        int pb = (int)(lab % NPC);
        g_pos_top[t]    = pt;
        g_pos_bottom[t] = pb;
        atomicAdd(&s_count[pt], 1);
        __syncthreads();

        if (t < 32) {
            int base = t * 7;
            int v[7], loc[7];
            int sum = 0;
#pragma unroll
            for (int i = 0; i < 7; i++) v[i] = s_count[base + i];
#pragma unroll
            for (int i = 0; i < 7; i++) { loc[i] = sum; sum += v[i]; }
            int run = sum;
#pragma unroll
            for (int o = 1; o < 32; o <<= 1) {
                int nb = __shfl_up_sync(0xFFFFFFFFu, run, o);
                if (t >= o) run += nb;
            }
            int excl = run - sum;
#pragma unroll
            for (int i = 0; i < 7; i++) {
                s_off[base + i]    = excl + loc[i];
                g_offset[base + i] = excl + loc[i];
            }
            if (t == 31) g_offset[NCLASSES] = excl + sum;
        }
        __syncthreads();
        if (t < NCLASSES) g_count[t] = s_count[t];
        int p = atomicAdd(&s_off[pt], 1);
        g_sorted[p] = t;
    }

    // all blocks: zero logit accumulators (float4 stores)
    int i = blockIdx.x * 1024 + t;
    int stride = gridDim.x * 1024;
    float4 z = make_float4(0.f, 0.f, 0.f, 0.f);
    for (int j = i; j < BATCH * NCLASSES / 4; j += stride)
        ((float4*)g_top_logits)[j] = z;
    for (int j = i; j < BATCH * NPC / 4; j += stride)
        ((float4*)g_bot_logits)[j] = z;
}

// ---------------- 2: fused main — bottom (TMA-bulk W) + top GEMM -------------
// grid 4096; per group of 8 bids: 7 bottom + 1 top.
// bottom index b in [0,3584): b = (c*8 + seg)*2 + chunk.
__global__ void __launch_bounds__(128) k_main(
    const float* __restrict__ X,    // [BATCH, NHID]
    const float* __restrict__ Wt,   // [NHID, NCLASSES]
    const float* __restrict__ Wb)   // [NCLASSES, NHID, NPC]
{
    __shared__ __align__(16) union {
        struct {
            float Wsm[2][TD * NPC];   // 2 x 14.4 KB
            float Xs[SCH][DLEN];      // 4 KB
            int   ids[SCH];
        } b;
        struct { float Xs[16][KLEN]; float Ws[16][NCLASSES]; } tp;
    } sm;
    __shared__ __align__(8) ull s_mbar[2];

    int bx = blockIdx.x;
    int g  = bx >> 3;
    int r  = bx & 7;
    bool is_top = (r == 7);
    int t = threadIdx.x, warp = t >> 5, lane = t & 31;

    if (!is_top) {
        // ===================== bottom =====================
        int b     = g * 7 + r;          // 0..3583
        int chunk = b & 1;
        int cs    = b >> 1;             // c*8 + seg
        int c     = cs >> 3;
        int seg   = cs & 7;
        int n = g_count[c];
        int s_begin = chunk * SCH;
        if (s_begin >= n) return;       // spare chunk block: exit
        int base = g_offset[c];
        int d0   = seg * DLEN;

        int c0 = warp * 64 + lane;      // always < 224
        int c1 = c0 + 32;
        bool v1 = (c1 < NPC);
        int c1c = v1 ? c1 : 224;

        const float* W = Wb + (size_t)c * NHID * NPC + (size_t)d0 * NPC;
        uint32_t smW[2];
        smW[0] = (uint32_t)__cvta_generic_to_shared(&sm.b.Wsm[0][0]);
        smW[1] = (uint32_t)__cvta_generic_to_shared(&sm.b.Wsm[1][0]);
        uint32_t mb[2];
        mb[0] = (uint32_t)__cvta_generic_to_shared(&s_mbar[0]);
        mb[1] = (uint32_t)__cvta_generic_to_shared(&s_mbar[1]);

        if (t == 0) { mbar_init(mb[0], 1); mbar_init(mb[1], 1); }
        __syncthreads();
        int ph0 = 0, ph1 = 0;

        // chunk 0: one pass; chunk 1: all remaining passes (rare n>16)
        int s_end  = (chunk == 0) ? min(n, SCH) : n;
        for (int s0 = s_begin; s0 < s_end; s0 += SCH) {
            int ns = min(SCH, n - s0);
            __syncthreads();
            if (t < ns) sm.b.ids[t] = g_sorted[base + s0 + t];
            __syncthreads();

            // stage X rows (float4 coalesced), zero-fill unused sample slots
            for (int i = t; i < SCH * 32; i += 128) {
                int s = i >> 5, q = i & 31;
                float4 val = make_float4(0.f, 0.f, 0.f, 0.f);
                if (s < ns)
                    val = ((const float4*)(X + (size_t)sm.b.ids[s] * NHID + d0))[q];
                ((float4*)&sm.b.Xs[s][0])[q] = val;
            }

            // prefetch weight tile 0 via TMA bulk (one instruction)
            if (t == 0) {
                mbar_expect_tx(mb[0], WBYTES);
                tma_bulk_1d(smW[0], W, WBYTES, mb[0]);
            }
            __syncthreads();    // X staging visible to all

            float acc0[SCH], acc1[SCH];
#pragma unroll
            for (int s = 0; s < SCH; s++) { acc0[s] = 0.f; acc1[s] = 0.f; }

#pragma unroll
            for (int tile = 0; tile < NTILE; tile++) {
                int buf = tile & 1;
                // issue tile+1 into the other buffer (free: consumed at
                // tile-1 and followed by that tile's __syncthreads)
                if (tile + 1 < NTILE && t == 0) {
                    int nbuf = (tile + 1) & 1;
                    mbar_expect_tx(mb[nbuf], WBYTES);
                    tma_bulk_1d(smW[nbuf],
                                (const void*)(W + (size_t)(tile + 1) * TD * NPC),
                                WBYTES, mb[nbuf]);
                }
                // wait for this tile's data
                mbar_wait(mb[buf], (buf == 0) ? ph0 : ph1);
                if (buf == 0) ph0 ^= 1; else ph1 ^= 1;

                const float* Wsm = sm.b.Wsm[buf];
                int tbase = tile * TD;
#pragma unroll
                for (int dq = 0; dq < TD; dq += 4) {
                    float w0[4], w1[4];
#pragma unroll
                    for (int k = 0; k < 4; k++) {
                        w0[k] = Wsm[(dq + k) * NPC + c0];
                        w1[k] = Wsm[(dq + k) * NPC + c1c];
                    }
#pragma unroll
                    for (int s = 0; s < SCH; s++) {
                        float4 x = *(const float4*)&sm.b.Xs[s][tbase + dq];
                        acc0[s] += x.x * w0[0]; acc1[s] += x.x * w1[0];
                        acc0[s] += x.y * w0[1]; acc1[s] += x.y * w1[1];
                        acc0[s] += x.z * w0[2]; acc1[s] += x.z * w1[2];
                        acc0[s] += x.w * w0[3]; acc1[s] += x.w * w1[3];
                    }
                }
                __syncthreads();   // all consumed: buffer reusable next issue
            }

            for (int s = 0; s < ns; s++) {
                int sid = sm.b.ids[s];
                atomicAdd(&g_bot_logits[sid * NPC + c0], acc0[s]);
                if (v1) atomicAdd(&g_bot_logits[sid * NPC + c1], acc1[s]);
            }
        }
    } else {
        // ===================== top GEMM =====================
        int tb = g;                      // 0..511
        int r0 = (tb >> 3) * 16;
        int k0 = (tb & 7) * KLEN;

        for (int i = t; i < 16 * 32; i += 128) {
            int rr = i >> 5, q = i & 31;
            ((float4*)&sm.tp.Xs[rr][0])[q] =
                ((const float4*)(X + (size_t)(r0 + rr) * NHID + k0))[q];
        }

        float acc[4][7];
#pragma unroll
        for (int rr = 0; rr < 4; rr++)
#pragma unroll
            for (int i = 0; i < 7; i++) acc[rr][i] = 0.f;

        for (int kc = 0; kc < KLEN; kc += 16) {
            __syncthreads();
            for (int i = t; i < 16 * NCLASSES; i += 128) {
                int kk = i / NCLASSES;
                int cc = i - kk * NCLASSES;
                sm.tp.Ws[kk][cc] = Wt[(size_t)(k0 + kc + kk) * NCLASSES + cc];
            }
            __syncthreads();
#pragma unroll
            for (int kq = 0; kq < 16; kq += 4) {
                float4 xv[4];
#pragma unroll
                for (int rr = 0; rr < 4; rr++)
                    xv[rr] = *(const float4*)&sm.tp.Xs[warp * 4 + rr][kc + kq];
                const float* xf = (const float*)xv;
#pragma unroll
                for (int j = 0; j < 4; j++) {
#pragma unroll
                    for (int i = 0; i < 7; i++) {
                        float wv = sm.tp.Ws[kq + j][lane + 32 * i];
#pragma unroll
                        for (int rr = 0; rr < 4; rr++)
                            acc[rr][i] += xf[rr * 4 + j] * wv;
                    }
                }
            }
        }

#pragma unroll
        for (int rr = 0; rr < 4; rr++) {
            int row = r0 + warp * 4 + rr;
#pragma unroll
            for (int i = 0; i < 7; i++)
                atomicAdd(&g_top_logits[row * NCLASSES + lane + 32 * i], acc[rr][i]);
        }
    }
}

// ---------------- 3: fused finish — both softmaxes + output ------------------
// one warp per sample
__global__ void __launch_bounds__(128) k_finish(
    const float* __restrict__ bt,   // [224]
    const float* __restrict__ bb,   // [NCLASSES, NPC]
    float* __restrict__ out)
{
    int sid  = (blockIdx.x * blockDim.x + threadIdx.x) >> 5;
    int lane = threadIdx.x & 31;
    if (sid >= BATCH) return;
    int c = g_pos_top[sid];

    // ---- top softmax over 224 classes (7 per lane) ----
    float lt[7];
    float mx = -CUDART_INF_F;
#pragma unroll
    for (int i = 0; i < 7; i++) {
        int cc = lane + 32 * i;
        lt[i] = g_top_logits[sid * NCLASSES + cc] + bt[cc];
        mx = fmaxf(mx, lt[i]);
    }
#pragma unroll
    for (int o = 16; o > 0; o >>= 1) mx = fmaxf(mx, __shfl_xor_sync(0xFFFFFFFFu, mx, o));
    float s = 0.f;
#pragma unroll
    for (int i = 0; i < 7; i++) s += __expf(lt[i] - mx);
#pragma unroll
    for (int o = 16; o > 0; o >>= 1) s += __shfl_xor_sync(0xFFFFFFFFu, s, o);

    float myv  = lt[c >> 5];
    float tgt  = __shfl_sync(0xFFFFFFFFu, myv, c & 31);
    float top_p = __expf(tgt - mx) / s;

    // ---- bottom softmax over 225 columns (8 per lane, last partial) ----
    float vb[8];
    float mxb = -CUDART_INF_F;
#pragma unroll
    for (int k = 0; k < 8; k++) {
        int col = lane + 32 * k;
        if (col < NPC) {
            vb[k] = g_bot_logits[sid * NPC + col] + bb[c * NPC + col];
            mxb = fmaxf(mxb, vb[k]);
        } else vb[k] = -CUDART_INF_F;
    }
#pragma unroll
    for (int o = 16; o > 0; o >>= 1) mxb = fmaxf(mxb, __shfl_xor_sync(0xFFFFFFFFu, mxb, o));
    float sb = 0.f;
#pragma unroll
    for (int k = 0; k < 8; k++) sb += __expf(vb[k] - mxb);
#pragma unroll
    for (int o = 16; o > 0; o >>= 1) sb += __shfl_xor_sync(0xFFFFFFFFu, sb, o);

    int pb = g_pos_bottom[sid];
    if (lane == (pb & 31))
        out[sid] = top_p * (__expf(vb[pb >> 5] - mxb) / sb);
}

// ---------------- launch -----------------------------------------------------
extern "C" void kernel_launch(void* const* d_in, const int* in_sizes, int n_in,
                              void* d_out, int out_size)
{
    const float* X   = (const float*)d_in[0];   // [1024, 1024]
    const void*  lab = d_in[1];                 // [1024] int32/int64
    const float* Wt  = (const float*)d_in[2];   // [1024, 224]
    const float* bt  = (const float*)d_in[3];   // [224]
    const float* Wb  = (const float*)d_in[4];   // [224, 1024, 225]
    const float* bb  = (const float*)d_in[5];   // [224, 225]
    float* out = (float*)d_out;

    k_init<<<112, 1024>>>(lab);
    k_main<<<ALL_BLOCKS, 128>>>(X, Wt, Wb);
    k_finish<<<BATCH / 4, 128>>>(bt, bb, out);
}